// round 8
// baseline (speedup 1.0000x reference)
#include <cuda_runtime.h>
#include <cuda_bf16.h>
#include <cstdint>

constexpr int B    = 32;
constexpr int H    = 1024;
constexpr int MEL  = 128;
constexpr int TENC = 512;
constexpr int TMEL = 400;
constexpr int H3   = 3 * H;

constexpr size_t OFF_GATE = (size_t)B * TMEL * MEL;
constexpr size_t OFF_MASK = OFF_GATE + (size_t)B * TMEL;

// ---------------- float4-packed weights: dst[(cg*(K/4)+k4)*32+cl] = W[cg*32+cl][4k4..] 
__device__ float4 P4ih0[(size_t)96 * 32  * 32 + 32];   // [3072 out][128 k]
__device__ float4 P4hh0[(size_t)96 * 256 * 32 + 32];   // [3072][1024]
__device__ float4 P4ih1[(size_t)96 * 256 * 32 + 32];
__device__ float4 P4hh1[(size_t)96 * 256 * 32 + 32];
__device__ float4 P4c  [(size_t)32 * 512 * 32 + 32];   // [1024][2048]
__device__ float4 P4p6 [(size_t)5  * 256 * 32 + 32];   // [160][1024] (mel+gate)
__device__ float4 P4at [(size_t)32 * 256 * 32 + 32];   // W_attn^T: out=c, k=j

// ---------------- states / partials ------------------------------------------
__device__ float g_h0[2][B * H];
__device__ float g_h1[2][B * H];
__device__ float g_decin[B * MEL];
__device__ float g_v[B * H];
__device__ float g_scores[B * TENC];
__device__ float g_ctx[B * H];
__device__ float g_co[B * H];

__device__ float pG[32][B][H3];
__device__ float vp[32][B * H];
__device__ float cp[32][B * H];
__device__ float p6p[32][B][160];

// barriers
__device__ unsigned g_bar_arrive = 0;
__device__ volatile unsigned g_bar_gen = 0;
__device__ volatile unsigned g_arr[152 * 8];
__device__ volatile unsigned g_release;

// ---------------- helpers ----------------------------------------------------
__device__ __forceinline__ float wsum(float v) {
    v += __shfl_xor_sync(0xffffffffu, v, 16);
    v += __shfl_xor_sync(0xffffffffu, v, 8);
    v += __shfl_xor_sync(0xffffffffu, v, 4);
    v += __shfl_xor_sync(0xffffffffu, v, 2);
    v += __shfl_xor_sync(0xffffffffu, v, 1);
    return v;
}
__device__ __forceinline__ float wmax(float v) {
    v = fmaxf(v, __shfl_xor_sync(0xffffffffu, v, 16));
    v = fmaxf(v, __shfl_xor_sync(0xffffffffu, v, 8));
    v = fmaxf(v, __shfl_xor_sync(0xffffffffu, v, 4));
    v = fmaxf(v, __shfl_xor_sync(0xffffffffu, v, 2));
    v = fmaxf(v, __shfl_xor_sync(0xffffffffu, v, 1));
    return v;
}
__device__ __forceinline__ float sigmoidf_(float x) { return 1.f / (1.f + expf(-x)); }

// legacy atomic barrier (re-launch safe); used once after init
__device__ __forceinline__ void abar(int nblk) {
    __syncthreads();
    if (threadIdx.x == 0) {
        __threadfence();
        unsigned gen = g_bar_gen;
        if (atomicAdd(&g_bar_arrive, 1u) == (unsigned)nblk - 1u) {
            g_bar_arrive = 0;
            __threadfence();
            g_bar_gen = gen + 1u;
        } else {
            while (g_bar_gen == gen) { __nanosleep(64); }
        }
        __threadfence();
    }
    __syncthreads();
}

// CG-style grid barrier: per-block arrive slots, block 0 scans, everyone else
// polls ONE broadcast word with backoff (no L2 flood).
__device__ __forceinline__ void sbar(int nblk, int bx, unsigned gen) {
    __syncthreads();
    if (threadIdx.x == 0) { __threadfence(); g_arr[bx * 8] = gen; }
    if (bx == 0) {
        if (threadIdx.x < 32) {
            for (;;) {
                bool ok = true;
                for (int i = threadIdx.x; i < nblk; i += 32)
                    ok &= (g_arr[i * 8] >= gen);
                if (__all_sync(0xffffffffu, ok)) break;
                __nanosleep(64);
            }
            if (threadIdx.x == 0) { __threadfence(); g_release = gen; }
        }
    } else if (threadIdx.x == 0) {
        while (g_release < gen) { __nanosleep(128); }
        __threadfence();
    }
    __syncthreads();
}

// GEMM micro-kernel: lane owns one output column; 32 batch accumulators.
// Weight = one coalesced float4/lane per 4-k group, double-buffered (__ldcs).
// XS is a compile-time activation stride -> immediate-offset batch loads.
template<int XS>
__device__ __forceinline__ void gemm32f4(const float4* __restrict__ W4,
                                         const float* __restrict__ X,
                                         int nk4, float* __restrict__ acc) {
    float4 w = __ldcs(W4);
#pragma unroll 1
    for (int k4 = 0; k4 < nk4; ++k4) {
        float4 wn = __ldcs(W4 + 32);     // prefetch next (pad makes overread safe)
        W4 += 32;
        const float* Xk = X + (k4 << 2);
#pragma unroll
        for (int bb = 0; bb < 32; ++bb) {
            float4 xv = *reinterpret_cast<const float4*>(Xk + bb * XS);
            acc[bb] = fmaf(w.x, xv.x, fmaf(w.y, xv.y,
                      fmaf(w.z, xv.z, fmaf(w.w, xv.w, acc[bb]))));
        }
        w = wn;
    }
}

// pack row-major W[j][k] (O x K) into float4 tiles: dst[(cg*(K/4)+k4)*32+cl]
__device__ void pack4_mat(const float* __restrict__ src, float4* __restrict__ dst,
                          int O, int K, int bx, int nblk, int tid,
                          float (*tile)[33]) {
    int x = tid & 31, y = (tid >> 5) & 15;
    int ntr = O >> 5, ntc = K >> 5, K4 = K >> 2;
    for (int t = bx; t < ntr * ntc; t += nblk) {
        int tr = t / ntc, tc = t % ntc;
        __syncthreads();
        tile[y][x]      = src[(size_t)(tr * 32 + y) * K + tc * 32 + x];
        tile[y + 16][x] = src[(size_t)(tr * 32 + y + 16) * K + tc * 32 + x];
        __syncthreads();
        if (tid < 256) {
            int xp = tid >> 5, cl = tid & 31;
            float4 v = make_float4(tile[cl][4 * xp + 0], tile[cl][4 * xp + 1],
                                   tile[cl][4 * xp + 2], tile[cl][4 * xp + 3]);
            dst[((size_t)tr * K4 + tc * 8 + xp) * 32 + cl] = v;
        }
    }
}

// transposed variant: element = src[k][cg*32+cl] (src is K x O row-major)
__device__ void pack4_matT(const float* __restrict__ src, float4* __restrict__ dst,
                           int O, int K, int bx, int nblk, int tid,
                           float (*tile)[33]) {
    int x = tid & 31, y = (tid >> 5) & 15;
    int ntr = O >> 5, ntc = K >> 5, K4 = K >> 2;
    for (int t = bx; t < ntr * ntc; t += nblk) {
        int tr = t / ntc, tc = t % ntc;
        __syncthreads();
        tile[y][x]      = src[(size_t)(tc * 32 + y) * O + tr * 32 + x];
        tile[y + 16][x] = src[(size_t)(tc * 32 + y + 16) * O + tr * 32 + x];
        __syncthreads();
        if (tid < 256) {
            int xp = tid >> 5, cl = tid & 31;
            float4 v = make_float4(tile[4 * xp + 0][cl], tile[4 * xp + 1][cl],
                                   tile[4 * xp + 2][cl], tile[4 * xp + 3][cl]);
            dst[((size_t)tr * K4 + tc * 8 + xp) * 32 + cl] = v;
        }
    }
}

// ---------------- main persistent kernel -------------------------------------
__global__ void __launch_bounds__(512, 1)
decoder_kernel(const float* __restrict__ enc_hidden,
               const float* __restrict__ enc_out,
               const int*   __restrict__ lens,
               const float* __restrict__ W_attn, const float* __restrict__ b_attn,
               const float* __restrict__ Wih0, const float* __restrict__ Whh0,
               const float* __restrict__ bih0, const float* __restrict__ bhh0,
               const float* __restrict__ Wih1, const float* __restrict__ Whh1,
               const float* __restrict__ bih1, const float* __restrict__ bhh1,
               const float* __restrict__ Wc,   const float* __restrict__ bc,
               const float* __restrict__ Wp,   const float* __restrict__ bp,
               const float* __restrict__ Wg,   const float* __restrict__ bg,
               float* __restrict__ out, int nblk) {
    __shared__ float tile[32][33];
    const int tid  = threadIdx.x;
    const int lane = tid & 31;
    const int wid  = tid >> 5;
    const int bx   = blockIdx.x;
    const int jw   = wid * nblk + bx;
    const int GW   = nblk * 16;
    const int gtid = bx * blockDim.x + tid;
    const int gsz  = nblk * blockDim.x;

    // ================= init =================
    pack4_mat (Wih0,   P4ih0, H3,  MEL,   bx, nblk, tid, tile);
    pack4_mat (Whh0,   P4hh0, H3,  H,     bx, nblk, tid, tile);
    pack4_mat (Wih1,   P4ih1, H3,  H,     bx, nblk, tid, tile);
    pack4_mat (Whh1,   P4hh1, H3,  H,     bx, nblk, tid, tile);
    pack4_mat (Wc,     P4c,   H,   2 * H, bx, nblk, tid, tile);
    pack4_mat (Wp,     P4p6,  MEL, H,     bx, nblk, tid, tile);   // cg 0..3
    pack4_matT(W_attn, P4at,  H,   H,     bx, nblk, tid, tile);

    // gate rows of P4p6 (cg 4): cl==0 -> Wg, else 0
    for (int d = gtid; d < 256 * 32; d += gsz) {
        int k4 = d >> 5, cl = d & 31;
        float4 v = make_float4(0.f, 0.f, 0.f, 0.f);
        if (cl == 0) v = make_float4(Wg[4 * k4], Wg[4 * k4 + 1], Wg[4 * k4 + 2], Wg[4 * k4 + 3]);
        P4p6[(size_t)(4 * 256 + k4) * 32 + cl] = v;
    }
    for (int i = gtid; i < B * H; i += gsz) {
        g_h0[0][i] = enc_hidden[i];
        g_h1[0][i] = enc_hidden[B * H + i];
    }
    for (int i = gtid; i < B * MEL; i += gsz) g_decin[i] = 0.f;
    for (int i = gtid; i < B * TMEL; i += gsz) {
        int b = i / TMEL, t = i - b * TMEL;
        out[OFF_MASK + i] = (t > lens[b]) ? 1.f : 0.f;
    }
    for (int i = gtid; i < 152 * 8; i += gsz) g_arr[i] = 0u;   // re-launch reset
    if (gtid == 0) g_release = 0u;
    abar(nblk);

    unsigned gen = 0;

    // ================= 400 autoregressive steps =================
    for (int step = 0; step < TMEL; ++step) {
        const int cur = step & 1, nxt = cur ^ 1;

        // ---- A: GRU0 GEMMs (192 x-side klen64 + 1536 h-side klen64) ----
        for (int job = jw; job < 1728; job += GW) {
            float acc[32];
#pragma unroll
            for (int i = 0; i < 32; ++i) acc[i] = 0.f;
            int jg, slot;
            if (job < 192) {
                jg = job >> 1; int kc = job & 1; slot = kc;
                gemm32f4<MEL>(P4ih0 + ((size_t)jg * 32 + kc * 16) * 32 + lane,
                              g_decin + kc * 64, 16, acc);
            } else {
                int q = job - 192;
                jg = q >> 4; int kc = q & 15; slot = 2 + kc;
                gemm32f4<H>(P4hh0 + ((size_t)jg * 256 + kc * 16) * 32 + lane,
                            g_h0[cur] + kc * 64, 16, acc);
            }
            const int j = jg * 32 + lane;
#pragma unroll 4
            for (int bb = 0; bb < 32; ++bb) pG[slot][bb][j] = acc[bb];
        }
        sbar(nblk, bx, ++gen);

        // ---- B: combine GRU0 ----
        for (int idx = gtid; idx < B * H; idx += gsz) {
            int b = idx >> 10, c = idx & (H - 1);
            float sx[3], sh[3];
#pragma unroll
            for (int g = 0; g < 3; ++g) {
                int j = g * H + c;
                sx[g] = pG[0][b][j] + pG[1][b][j];
                float s = 0.f;
#pragma unroll
                for (int p = 2; p < 18; ++p) s += pG[p][b][j];
                sh[g] = s;
            }
            float r = sigmoidf_(sx[0] + sh[0] + bih0[c] + bhh0[c]);
            float z = sigmoidf_(sx[1] + sh[1] + bih0[H + c] + bhh0[H + c]);
            float n = tanhf(sx[2] + bih0[2 * H + c] + r * (sh[2] + bhh0[2 * H + c]));
            g_h0[nxt][idx] = (1.f - z) * n + z * g_h0[cur][idx];
        }
        sbar(nblk, bx, ++gen);

        // ---- C: GRU1 GEMMs (1536 + 1536 jobs, klen64) ----
        for (int job = jw; job < 3072; job += GW) {
            float acc[32];
#pragma unroll
            for (int i = 0; i < 32; ++i) acc[i] = 0.f;
            int jg, slot;
            if (job < 1536) {
                jg = job >> 4; int kc = job & 15; slot = kc;
                gemm32f4<H>(P4ih1 + ((size_t)jg * 256 + kc * 16) * 32 + lane,
                            g_h0[nxt] + kc * 64, 16, acc);
            } else {
                int q = job - 1536;
                jg = q >> 4; int kc = q & 15; slot = 16 + kc;
                gemm32f4<H>(P4hh1 + ((size_t)jg * 256 + kc * 16) * 32 + lane,
                            g_h1[cur] + kc * 64, 16, acc);
            }
            const int j = jg * 32 + lane;
#pragma unroll 4
            for (int bb = 0; bb < 32; ++bb) pG[slot][bb][j] = acc[bb];
        }
        sbar(nblk, bx, ++gen);

        // ---- D: combine GRU1 ----
        for (int idx = gtid; idx < B * H; idx += gsz) {
            int b = idx >> 10, c = idx & (H - 1);
            float sx[3], sh[3];
#pragma unroll
            for (int g = 0; g < 3; ++g) {
                int j = g * H + c;
                float s1 = 0.f, s2 = 0.f;
#pragma unroll
                for (int p = 0; p < 16; ++p) s1 += pG[p][b][j];
#pragma unroll
                for (int p = 16; p < 32; ++p) s2 += pG[p][b][j];
                sx[g] = s1; sh[g] = s2;
            }
            float r = sigmoidf_(sx[0] + sh[0] + bih1[c] + bhh1[c]);
            float z = sigmoidf_(sx[1] + sh[1] + bih1[H + c] + bhh1[H + c]);
            float n = tanhf(sx[2] + bih1[2 * H + c] + r * (sh[2] + bhh1[2 * H + c]));
            g_h1[nxt][idx] = (1.f - z) * n + z * g_h1[cur][idx];
        }
        sbar(nblk, bx, ++gen);

        const float* h1n = g_h1[nxt];

        // ---- E: Pv  v = W_attn^T h1  (1024 jobs, klen32) ----
        for (int job = jw; job < 1024; job += GW) {
            int cg = job >> 5, kc = job & 31;
            float acc[32];
#pragma unroll
            for (int i = 0; i < 32; ++i) acc[i] = 0.f;
            gemm32f4<H>(P4at + ((size_t)cg * 256 + kc * 8) * 32 + lane,
                        h1n + kc * 32, 8, acc);
            const int c = cg * 32 + lane;
#pragma unroll 4
            for (int bb = 0; bb < 32; ++bb) vp[kc][bb * H + c] = acc[bb];
        }
        sbar(nblk, bx, ++gen);

        // ---- Ec: v = sum partials ----
        for (int idx = gtid; idx < B * H; idx += gsz) {
            float s = 0.f;
#pragma unroll
            for (int p = 0; p < 32; ++p) s += vp[p][idx];
            g_v[idx] = s;
        }
        sbar(nblk, bx, ++gen);

        // ---- P3: scores[b,t] = v[b,:] . enc_out[b,t,:]  (2048 jobs) ----
        for (int job = jw; job < 2048; job += GW) {
            const int b  = job >> 6;
            const int t0 = (job & 63) * 8;
            float acc[8];
#pragma unroll
            for (int i = 0; i < 8; ++i) acc[i] = 0.f;
            const float4* vb = reinterpret_cast<const float4*>(g_v + (size_t)b * H);
            const float4* Eb = reinterpret_cast<const float4*>(
                enc_out + ((size_t)b * TENC + t0) * H);
            for (int k = lane; k < 256; k += 32) {
                float4 vv = vb[k];
#pragma unroll
                for (int t = 0; t < 8; ++t) {
                    float4 ev = Eb[(size_t)t * 256 + k];
                    acc[t] = fmaf(vv.x, ev.x, fmaf(vv.y, ev.y,
                             fmaf(vv.z, ev.z, fmaf(vv.w, ev.w, acc[t]))));
                }
            }
#pragma unroll
            for (int t = 0; t < 8; ++t) {
                float s = wsum(acc[t]);
                if (lane == t) g_scores[b * TENC + t0 + t] = s;
            }
        }
        sbar(nblk, bx, ++gen);

        // ---- P4: softmax (per-warp) + context (1024 jobs) ----
        for (int job = jw; job < 1024; job += GW) {
            const int b  = job >> 5;
            const int hg = (job & 31) * 32;
            const float* srow = g_scores + b * TENC;
            float sc[16];
            float mx = -1e30f;
#pragma unroll
            for (int i = 0; i < 16; ++i) {
                sc[i] = srow[i * 32 + lane];
                mx = fmaxf(mx, sc[i]);
            }
            mx = wmax(mx);
            float sm = 0.f;
#pragma unroll
            for (int i = 0; i < 16; ++i) { sc[i] = expf(sc[i] - mx); sm += sc[i]; }
            sm = wsum(sm);
            const float inv = 1.f / sm;

            float acc = 0.f;
            const float* ep = enc_out + (size_t)b * TENC * H + hg + lane;
#pragma unroll
            for (int i = 0; i < 16; ++i) {
                float pv = sc[i] * inv;
#pragma unroll 8
                for (int tt = 0; tt < 32; ++tt) {
                    float p  = __shfl_sync(0xffffffffu, pv, tt);
                    float ev = ep[(size_t)(i * 32 + tt) * H];
                    acc = fmaf(p, ev, acc);
                }
            }
            g_ctx[(size_t)b * H + hg + lane] = acc;
        }
        sbar(nblk, bx, ++gen);

        // ---- P5: co GEMM over [h1; ctx] (1024 jobs, klen64) ----
        for (int job = jw; job < 1024; job += GW) {
            int cg = job >> 5, kc = job & 31;
            float acc[32];
#pragma unroll
            for (int i = 0; i < 32; ++i) acc[i] = 0.f;
            const float* X = (kc < 16) ? (h1n + kc * 64) : (g_ctx + (kc - 16) * 64);
            gemm32f4<H>(P4c + ((size_t)cg * 512 + kc * 16) * 32 + lane, X, 16, acc);
            const int c = cg * 32 + lane;
#pragma unroll 4
            for (int bb = 0; bb < 32; ++bb) cp[kc][bb * H + c] = acc[bb];
        }
        sbar(nblk, bx, ++gen);

        // ---- P5c: co = tanh(sum + bc) ----
        for (int idx = gtid; idx < B * H; idx += gsz) {
            int c = idx & (H - 1);
            float s = 0.f;
#pragma unroll
            for (int p = 0; p < 32; ++p) s += cp[p][idx];
            g_co[idx] = tanhf(s + bc[c]);
        }
        sbar(nblk, bx, ++gen);

        // ---- P6: mel/gate GEMM (160 jobs, klen32) ----
        for (int job = jw; job < 160; job += GW) {
            int cg = job % 5, kc = job / 5;
            float acc[32];
#pragma unroll
            for (int i = 0; i < 32; ++i) acc[i] = 0.f;
            gemm32f4<H>(P4p6 + ((size_t)cg * 256 + kc * 8) * 32 + lane,
                        g_co + kc * 32, 8, acc);
            const int c = cg * 32 + lane;
#pragma unroll 4
            for (int bb = 0; bb < 32; ++bb) p6p[kc][bb][c] = acc[bb];
        }
        sbar(nblk, bx, ++gen);

        // ---- P6c: bias + mask + outputs + next decoder input ----
        for (int idx = gtid; idx < B * 160; idx += gsz) {
            int b = idx / 160, m = idx - b * 160;
            if (m > MEL) continue;
            float s = 0.f;
#pragma unroll
            for (int p = 0; p < 32; ++p) s += p6p[p][b][m];
            const bool msk = step > lens[b];
            if (m < MEL) {
                float val = s + bp[m];
                g_decin[b * MEL + m] = val;
                out[((size_t)b * TMEL + step) * MEL + m] = msk ? 0.f : val;
            } else {
                float gv = s + bg[0];
                out[OFF_GATE + (size_t)b * TMEL + step] = msk ? 1000.f : gv;
            }
        }
        sbar(nblk, bx, ++gen);
    }
}

// ---------------- host launch -------------------------------------------------
extern "C" void kernel_launch(void* const* d_in, const int* in_sizes, int n_in,
                              void* d_out, int out_size) {
    (void)in_sizes; (void)n_in; (void)out_size;
    int dev = 0;
    cudaGetDevice(&dev);
    int sms = 0;
    cudaDeviceGetAttribute(&sms, cudaDevAttrMultiProcessorCount, dev);
    if (sms <= 0) sms = 148;
    if (sms > 152) sms = 152;

    decoder_kernel<<<sms, 512>>>(
        (const float*)d_in[0],   // encoder_hidden [4,B,H]
        (const float*)d_in[1],   // encoder_outputs [B,TENC,H]
        (const int*)d_in[3],     // mel_spec_lens [B]   (d_in[2] = y, unused)
        (const float*)d_in[4],  (const float*)d_in[5],    // W_attn, b_attn
        (const float*)d_in[6],  (const float*)d_in[7],    // W_ih0, W_hh0
        (const float*)d_in[8],  (const float*)d_in[9],    // b_ih0, b_hh0
        (const float*)d_in[10], (const float*)d_in[11],   // W_ih1, W_hh1
        (const float*)d_in[12], (const float*)d_in[13],   // b_ih1, b_hh1
        (const float*)d_in[14], (const float*)d_in[15],   // Wc, bc
        (const float*)d_in[16], (const float*)d_in[17],   // Wp, bp
        (const float*)d_in[18], (const float*)d_in[19],   // Wg, bg
        (float*)d_out, sms);
}

// round 9
// speedup vs baseline: 1.4395x; 1.4395x over previous
#include <cuda_runtime.h>
#include <cuda_bf16.h>
#include <cstdint>

constexpr int B    = 32;
constexpr int H    = 1024;
constexpr int MEL  = 128;
constexpr int TENC = 512;
constexpr int TMEL = 400;
constexpr int H4   = H / 4;

constexpr size_t OFF_GATE = (size_t)B * TMEL * MEL;
constexpr size_t OFF_MASK = OFF_GATE + (size_t)B * TMEL;

// ---------------- device scratch (no allocations allowed) -------------------
__device__ float g_WT[(size_t)H * H];       // W_attn^T: g_WT[c*H+j] = W_attn[j*H+c]
__device__ float g_h0[2][B * H];
__device__ float g_h1[2][B * H];
__device__ float g_decin[B * MEL];
__device__ float g_v[B * H];
__device__ float g_scores[B * TENC];
__device__ float g_ctx[B * H];
__device__ float g_co[B * H];

// barriers
__device__ unsigned g_bar_arrive = 0;
__device__ volatile unsigned g_bar_gen = 0;
__device__ volatile unsigned g_arr[152 * 8];
__device__ volatile unsigned g_release;

// ---------------- helpers ----------------------------------------------------
__device__ __forceinline__ float wsum(float v) {
    v += __shfl_xor_sync(0xffffffffu, v, 16);
    v += __shfl_xor_sync(0xffffffffu, v, 8);
    v += __shfl_xor_sync(0xffffffffu, v, 4);
    v += __shfl_xor_sync(0xffffffffu, v, 2);
    v += __shfl_xor_sync(0xffffffffu, v, 1);
    return v;
}
__device__ __forceinline__ float wmax(float v) {
    v = fmaxf(v, __shfl_xor_sync(0xffffffffu, v, 16));
    v = fmaxf(v, __shfl_xor_sync(0xffffffffu, v, 8));
    v = fmaxf(v, __shfl_xor_sync(0xffffffffu, v, 4));
    v = fmaxf(v, __shfl_xor_sync(0xffffffffu, v, 2));
    v = fmaxf(v, __shfl_xor_sync(0xffffffffu, v, 1));
    return v;
}
__device__ __forceinline__ float dot4(float4 a, float4 b, float acc) {
    acc = fmaf(a.x, b.x, acc);
    acc = fmaf(a.y, b.y, acc);
    acc = fmaf(a.z, b.z, acc);
    acc = fmaf(a.w, b.w, acc);
    return acc;
}
__device__ __forceinline__ float sigmoidf_(float x) { return 1.f / (1.f + expf(-x)); }

// legacy atomic barrier (re-launch safe); used once after init
__device__ __forceinline__ void abar(int nblk) {
    __syncthreads();
    if (threadIdx.x == 0) {
        __threadfence();
        unsigned gen = g_bar_gen;
        if (atomicAdd(&g_bar_arrive, 1u) == (unsigned)nblk - 1u) {
            g_bar_arrive = 0;
            __threadfence();
            g_bar_gen = gen + 1u;
        } else {
            while (g_bar_gen == gen) { __nanosleep(64); }
        }
        __threadfence();
    }
    __syncthreads();
}

// grid barrier: per-block arrive slots, block 0 scans, all others poll one
// broadcast release word with backoff.
__device__ __forceinline__ void sbar(int nblk, int bx, unsigned gen) {
    __syncthreads();
    if (threadIdx.x == 0) { __threadfence(); g_arr[bx * 8] = gen; }
    if (bx == 0) {
        if (threadIdx.x < 32) {
            for (;;) {
                bool ok = true;
                for (int i = threadIdx.x; i < nblk; i += 32)
                    ok &= (g_arr[i * 8] >= gen);
                if (__all_sync(0xffffffffu, ok)) break;
                __nanosleep(32);
            }
            if (threadIdx.x == 0) { __threadfence(); g_release = gen; }
        }
    } else if (threadIdx.x == 0) {
        while (g_release < gen) { __nanosleep(64); }
        __threadfence();
    }
    __syncthreads();
}

// ---------------- merged GRU cell: one job = (column j, 8 batches) ----------
// Full-k warp dot for all 3 gates at once; shuffle-reduce; direct state write.
__device__ __forceinline__ void gru_job(
    int j, int b0, int lane,
    const float* __restrict__ x, int XD,
    const float* __restrict__ hprev, float* __restrict__ hnew,
    const float* __restrict__ Wih, const float* __restrict__ Whh,
    const float* __restrict__ bih, const float* __restrict__ bhh)
{
    const int XD4 = XD >> 2;
    float ar[8], az[8], ani[8], anh[8];
#pragma unroll
    for (int i = 0; i < 8; ++i) { ar[i] = 0.f; az[i] = 0.f; ani[i] = 0.f; anh[i] = 0.f; }

    {   // input side: ir, iz, in
        const float4* wr = reinterpret_cast<const float4*>(Wih + (size_t)j * XD);
        const float4* wz = reinterpret_cast<const float4*>(Wih + (size_t)(H + j) * XD);
        const float4* wn = reinterpret_cast<const float4*>(Wih + (size_t)(2 * H + j) * XD);
        const float4* x4 = reinterpret_cast<const float4*>(x);
        for (int k = lane; k < XD4; k += 32) {
            float4 r4 = wr[k], z4 = wz[k], n4 = wn[k];
#pragma unroll
            for (int bb = 0; bb < 8; ++bb) {
                float4 xv = x4[(size_t)(b0 + bb) * XD4 + k];
                ar[bb]  = dot4(r4, xv, ar[bb]);
                az[bb]  = dot4(z4, xv, az[bb]);
                ani[bb] = dot4(n4, xv, ani[bb]);
            }
        }
    }
    {   // hidden side: hr, hz, hn
        const float4* wr = reinterpret_cast<const float4*>(Whh + (size_t)j * H);
        const float4* wz = reinterpret_cast<const float4*>(Whh + (size_t)(H + j) * H);
        const float4* wn = reinterpret_cast<const float4*>(Whh + (size_t)(2 * H + j) * H);
        const float4* h4 = reinterpret_cast<const float4*>(hprev);
        for (int k = lane; k < H4; k += 32) {
            float4 r4 = wr[k], z4 = wz[k], n4 = wn[k];
#pragma unroll
            for (int bb = 0; bb < 8; ++bb) {
                float4 hv = h4[(size_t)(b0 + bb) * H4 + k];
                ar[bb]  = dot4(r4, hv, ar[bb]);
                az[bb]  = dot4(z4, hv, az[bb]);
                anh[bb] = dot4(n4, hv, anh[bb]);
            }
        }
    }
    const float br  = bih[j] + bhh[j];
    const float bz  = bih[H + j] + bhh[H + j];
    const float bni = bih[2 * H + j];
    const float bnh = bhh[2 * H + j];
#pragma unroll
    for (int bb = 0; bb < 8; ++bb) {
        float r  = wsum(ar[bb]);
        float z  = wsum(az[bb]);
        float ni = wsum(ani[bb]);
        float nh = wsum(anh[bb]);
        if (lane == bb) {
            float rr = sigmoidf_(r + br);
            float zz = sigmoidf_(z + bz);
            float nn = tanhf(ni + bni + rr * (nh + bnh));
            const int idx = (b0 + bb) * H + j;
            hnew[idx] = (1.f - zz) * nn + zz * hprev[idx];
        }
    }
}

// ---------------- main persistent kernel -------------------------------------
__global__ void __launch_bounds__(512, 1)
decoder_kernel(const float* __restrict__ enc_hidden,
               const float* __restrict__ enc_out,
               const int*   __restrict__ lens,
               const float* __restrict__ W_attn, const float* __restrict__ b_attn,
               const float* __restrict__ Wih0, const float* __restrict__ Whh0,
               const float* __restrict__ bih0, const float* __restrict__ bhh0,
               const float* __restrict__ Wih1, const float* __restrict__ Whh1,
               const float* __restrict__ bih1, const float* __restrict__ bhh1,
               const float* __restrict__ Wc,   const float* __restrict__ bc,
               const float* __restrict__ Wp,   const float* __restrict__ bp,
               const float* __restrict__ Wg,   const float* __restrict__ bg,
               float* __restrict__ out, int nblk) {
    const int tid  = threadIdx.x;
    const int lane = tid & 31;
    const int wid  = tid >> 5;
    const int bx   = blockIdx.x;
    // quad mapping: 4 warps (one per SMSP) share the same output column j,
    // covering batch quarters -> weight rows hit L1 3 of 4 times.
    const int quad = wid >> 2;               // 0..3
    const int b0q  = (wid & 3) * 8;          // batch quarter
    const int jstart = bx + quad * nblk;
    const int jstep  = 4 * nblk;
    // flat mapping for non-weight phases
    const int jwf = wid * nblk + bx;
    const int GW  = nblk * 16;
    const int gtid = bx * blockDim.x + tid;
    const int gsz  = nblk * blockDim.x;

    // ================= init =================
    for (int i = gtid; i < H * H; i += gsz) {
        int c = i >> 10, j = i & (H - 1);
        g_WT[i] = W_attn[(size_t)j * H + c];
    }
    for (int i = gtid; i < B * H; i += gsz) {
        g_h0[0][i] = enc_hidden[i];
        g_h1[0][i] = enc_hidden[B * H + i];
    }
    for (int i = gtid; i < B * MEL; i += gsz) g_decin[i] = 0.f;
    for (int i = gtid; i < B * TMEL; i += gsz) {
        int b = i / TMEL, t = i - b * TMEL;
        out[OFF_MASK + i] = (t > lens[b]) ? 1.f : 0.f;
    }
    for (int i = gtid; i < 152 * 8; i += gsz) g_arr[i] = 0u;
    if (gtid == 0) g_release = 0u;
    abar(nblk);

    unsigned gen = 0;

    // ================= 400 autoregressive steps =================
    for (int step = 0; step < TMEL; ++step) {
        const int cur = step & 1, nxt = cur ^ 1;

        // ---- GRU layer 0 (merged gates, direct write) ----
        for (int j = jstart; j < H; j += jstep)
            gru_job(j, b0q, lane, g_decin, MEL, g_h0[cur], g_h0[nxt],
                    Wih0, Whh0, bih0, bhh0);
        sbar(nblk, bx, ++gen);

        // ---- GRU layer 1 ----
        for (int j = jstart; j < H; j += jstep)
            gru_job(j, b0q, lane, g_h0[nxt], H, g_h1[cur], g_h1[nxt],
                    Wih1, Whh1, bih1, bhh1);
        sbar(nblk, bx, ++gen);

        const float* h1n = g_h1[nxt];

        // ---- Pv: v[b,c] = sum_j h1[b,j] * W_attn[j,c] (bias drops in softmax) ----
        for (int c = jstart; c < H; c += jstep) {
            float acc[8];
#pragma unroll
            for (int i = 0; i < 8; ++i) acc[i] = 0.f;
            const float4* wk = reinterpret_cast<const float4*>(g_WT + (size_t)c * H);
            const float4* h4 = reinterpret_cast<const float4*>(h1n);
            for (int k = lane; k < H4; k += 32) {
                float4 wv = wk[k];
#pragma unroll
                for (int bb = 0; bb < 8; ++bb)
                    acc[bb] = dot4(wv, h4[(size_t)(b0q + bb) * H4 + k], acc[bb]);
            }
#pragma unroll
            for (int bb = 0; bb < 8; ++bb) {
                float s = wsum(acc[bb]);
                if (lane == bb) g_v[(b0q + bb) * H + c] = s;
            }
        }
        sbar(nblk, bx, ++gen);

        // ---- P3: scores[b,t] = v[b,:] . enc_out[b,t,:]  (2048 jobs, flat) ----
        for (int job = jwf; job < 2048; job += GW) {
            const int b  = job >> 6;
            const int t0 = (job & 63) * 8;
            float acc[8];
#pragma unroll
            for (int i = 0; i < 8; ++i) acc[i] = 0.f;
            const float4* vb = reinterpret_cast<const float4*>(g_v + (size_t)b * H);
            const float4* Eb = reinterpret_cast<const float4*>(
                enc_out + ((size_t)b * TENC + t0) * H);
            for (int k = lane; k < H4; k += 32) {
                float4 vv = vb[k];
#pragma unroll
                for (int t = 0; t < 8; ++t) {
                    float4 ev = Eb[(size_t)t * H4 + k];
                    acc[t] = fmaf(vv.x, ev.x, fmaf(vv.y, ev.y,
                             fmaf(vv.z, ev.z, fmaf(vv.w, ev.w, acc[t]))));
                }
            }
#pragma unroll
            for (int t = 0; t < 8; ++t) {
                float s = wsum(acc[t]);
                if (lane == t) g_scores[b * TENC + t0 + t] = s;
            }
        }
        sbar(nblk, bx, ++gen);

        // ---- P4: softmax (per-warp) + context (1024 jobs, flat) ----
        for (int job = jwf; job < 1024; job += GW) {
            const int b  = job >> 5;
            const int hg = (job & 31) * 32;
            const float* srow = g_scores + b * TENC;
            float sc[16];
            float mx = -1e30f;
#pragma unroll
            for (int i = 0; i < 16; ++i) {
                sc[i] = srow[i * 32 + lane];
                mx = fmaxf(mx, sc[i]);
            }
            mx = wmax(mx);
            float sm = 0.f;
#pragma unroll
            for (int i = 0; i < 16; ++i) { sc[i] = expf(sc[i] - mx); sm += sc[i]; }
            sm = wsum(sm);
            const float inv = 1.f / sm;

            float acc0 = 0.f, acc1 = 0.f;
            const float* ep = enc_out + (size_t)b * TENC * H + hg + lane;
#pragma unroll
            for (int i = 0; i < 8; ++i) {
                float pv0 = sc[i] * inv;
                float pv1 = sc[i + 8] * inv;
#pragma unroll 8
                for (int tt = 0; tt < 32; ++tt) {
                    float p0 = __shfl_sync(0xffffffffu, pv0, tt);
                    float p1 = __shfl_sync(0xffffffffu, pv1, tt);
                    float e0 = ep[(size_t)(i * 32 + tt) * H];
                    float e1 = ep[(size_t)((i + 8) * 32 + tt) * H];
                    acc0 = fmaf(p0, e0, acc0);
                    acc1 = fmaf(p1, e1, acc1);
                }
            }
            g_ctx[(size_t)b * H + hg + lane] = acc0 + acc1;
        }
        sbar(nblk, bx, ++gen);

        // ---- P5: co = tanh([h1; ctx] @ Wc^T + bc)  (quad mapping) ----
        for (int j = jstart; j < H; j += jstep) {
            float acc[8];
#pragma unroll
            for (int i = 0; i < 8; ++i) acc[i] = 0.f;
            const float4* w1 = reinterpret_cast<const float4*>(Wc + (size_t)j * 2 * H);
            const float4* w2 = w1 + H4;
            const float4* h4 = reinterpret_cast<const float4*>(h1n);
            const float4* c4 = reinterpret_cast<const float4*>(g_ctx);
            for (int k = lane; k < H4; k += 32) {
                float4 wv = w1[k];
#pragma unroll
                for (int bb = 0; bb < 8; ++bb)
                    acc[bb] = dot4(wv, h4[(size_t)(b0q + bb) * H4 + k], acc[bb]);
            }
            for (int k = lane; k < H4; k += 32) {
                float4 wv = w2[k];
#pragma unroll
                for (int bb = 0; bb < 8; ++bb)
                    acc[bb] = dot4(wv, c4[(size_t)(b0q + bb) * H4 + k], acc[bb]);
            }
            const float bcv = bc[j];
#pragma unroll
            for (int bb = 0; bb < 8; ++bb) {
                float s = wsum(acc[bb]);
                if (lane == bb) g_co[(b0q + bb) * H + j] = tanhf(s + bcv);
            }
        }
        sbar(nblk, bx, ++gen);

        // ---- P6: mel + gate projections, outputs, next decin (516 jobs) ----
        for (int job = jwf; job < 516; job += GW) {
            const int c  = job >> 2;            // 0..128 (128 = gate)
            const int b0 = (job & 3) * 8;
            float acc[8];
#pragma unroll
            for (int i = 0; i < 8; ++i) acc[i] = 0.f;
            const float4* wp = reinterpret_cast<const float4*>(
                (c < MEL) ? (Wp + (size_t)c * H) : Wg);
            const float4* co4 = reinterpret_cast<const float4*>(g_co);
            for (int k = lane; k < H4; k += 32) {
                float4 wv = wp[k];
#pragma unroll
                for (int bb = 0; bb < 8; ++bb)
                    acc[bb] = dot4(wv, co4[(size_t)(b0 + bb) * H4 + k], acc[bb]);
            }
            const float bias = (c < MEL) ? bp[c] : bg[0];
#pragma unroll
            for (int bb = 0; bb < 8; ++bb) {
                float s = wsum(acc[bb]);
                if (lane == bb) {
                    const int b = b0 + bb;
                    const bool msk = step > lens[b];
                    if (c < MEL) {
                        const float val = s + bias;
                        g_decin[b * MEL + c] = val;
                        out[((size_t)b * TMEL + step) * MEL + c] = msk ? 0.f : val;
                    } else {
                        out[OFF_GATE + (size_t)b * TMEL + step] = msk ? 1000.f : (s + bias);
                    }
                }
            }
        }
        sbar(nblk, bx, ++gen);
    }
}

// ---------------- host launch -------------------------------------------------
extern "C" void kernel_launch(void* const* d_in, const int* in_sizes, int n_in,
                              void* d_out, int out_size) {
    (void)in_sizes; (void)n_in; (void)out_size;
    int dev = 0;
    cudaGetDevice(&dev);
    int sms = 0;
    cudaDeviceGetAttribute(&sms, cudaDevAttrMultiProcessorCount, dev);
    if (sms <= 0) sms = 148;
    if (sms > 152) sms = 152;

    decoder_kernel<<<sms, 512>>>(
        (const float*)d_in[0],   // encoder_hidden [4,B,H]
        (const float*)d_in[1],   // encoder_outputs [B,TENC,H]
        (const int*)d_in[3],     // mel_spec_lens [B]   (d_in[2] = y, unused)
        (const float*)d_in[4],  (const float*)d_in[5],    // W_attn, b_attn
        (const float*)d_in[6],  (const float*)d_in[7],    // W_ih0, W_hh0
        (const float*)d_in[8],  (const float*)d_in[9],    // b_ih0, b_hh0
        (const float*)d_in[10], (const float*)d_in[11],   // W_ih1, W_hh1
        (const float*)d_in[12], (const float*)d_in[13],   // b_ih1, b_hh1
        (const float*)d_in[14], (const float*)d_in[15],   // Wc, bc
        (const float*)d_in[16], (const float*)d_in[17],   // Wp, bp
        (const float*)d_in[18], (const float*)d_in[19],   // Wg, bg
        (float*)d_out, sms);
}